// round 1
// baseline (speedup 1.0000x reference)
#include <cuda_runtime.h>
#include <math.h>

#define B  8
#define V  32000
#define S  512
#define NC 125          // number of V-chunks
#define VC (V / NC)     // 256 v per chunk
#define BSN (B * S)     // 4096 (b,s) columns
#define P  (S - 4)      // 508 n-gram windows

// -------- scratch (device globals; no allocation allowed) --------
__device__ float g_m [NC * BSN];   // per-chunk running max        [c][bs]
__device__ float g_d [NC * BSN];   // per-chunk sum exp(x - m)     [c][bs]
__device__ int   g_ix[NC * BSN];   // per-chunk argmax             [c][bs]
__device__ int   g_tok[BSN];       // argmax token per (b,s)
__device__ float g_pen[BSN];       // -log(clip(1 - p_tok))
__device__ float g_bloss[B];       // per-batch masked loss

// ================================================================
// Kernel 1: streaming online softmax partials + argmax, per V-chunk
// grid = (NC, B), block = 128 threads, thread owns 4 consecutive s.
// ================================================================
__global__ __launch_bounds__(128) void k_partial(const float* __restrict__ pred)
{
    const int c = blockIdx.x;
    const int b = blockIdx.y;
    const int t = threadIdx.x;
    const int s0 = t * 4;

    const float* p = pred + (size_t)(b * V + c * VC) * S + s0;

    float m0 = -INFINITY, m1 = -INFINITY, m2 = -INFINITY, m3 = -INFINITY;
    float d0 = 0.f, d1 = 0.f, d2 = 0.f, d3 = 0.f;
    int   i0 = 0,   i1 = 0,   i2 = 0,   i3 = 0;

    int v = c * VC;
#pragma unroll 8
    for (int vv = 0; vv < VC; vv++, v++) {
        float4 x = *reinterpret_cast<const float4*>(p);
        p += S;

        // online softmax update, one exp per element:
        //   a = x - m; e = exp(-|a|)
        //   a<=0: d += e          (e = exp(a))
        //   a> 0: d = d*e + 1     (e = exp(-a)), m = x, idx = v
        {
            float a = x.x - m0;
            float e = __expf(-fabsf(a));
            bool  g = a > 0.0f;
            d0 = g ? fmaf(d0, e, 1.0f) : (d0 + e);
            i0 = g ? v : i0;
            m0 = fmaxf(m0, x.x);
        }
        {
            float a = x.y - m1;
            float e = __expf(-fabsf(a));
            bool  g = a > 0.0f;
            d1 = g ? fmaf(d1, e, 1.0f) : (d1 + e);
            i1 = g ? v : i1;
            m1 = fmaxf(m1, x.y);
        }
        {
            float a = x.z - m2;
            float e = __expf(-fabsf(a));
            bool  g = a > 0.0f;
            d2 = g ? fmaf(d2, e, 1.0f) : (d2 + e);
            i2 = g ? v : i2;
            m2 = fmaxf(m2, x.z);
        }
        {
            float a = x.w - m3;
            float e = __expf(-fabsf(a));
            bool  g = a > 0.0f;
            d3 = g ? fmaf(d3, e, 1.0f) : (d3 + e);
            i3 = g ? v : i3;
            m3 = fmaxf(m3, x.w);
        }
    }

    const int base = c * BSN + b * S + s0;   // 16B aligned (s0 % 4 == 0)
    *reinterpret_cast<float4*>(&g_m[base]) = make_float4(m0, m1, m2, m3);
    *reinterpret_cast<float4*>(&g_d[base]) = make_float4(d0, d1, d2, d3);
    *reinterpret_cast<int4*>  (&g_ix[base]) = make_int4(i0, i1, i2, i3);
}

// ================================================================
// Kernel 2: combine chunk partials -> token + penalty per (b,s)
// grid = BSN/256 blocks of 256; one thread per (b,s) column.
// ================================================================
__global__ __launch_bounds__(256) void k_combine()
{
    const int bs = blockIdx.x * 256 + threadIdx.x;

    // global max / argmax (ascending chunk order + strict '>' keeps
    // the first occurrence, matching jnp.argmax)
    float m = -INFINITY;
    int best = 0;
    for (int c = 0; c < NC; c++) {
        float mc = g_m[c * BSN + bs];
        if (mc > m) { m = mc; best = g_ix[c * BSN + bs]; }
    }

    // combine logsumexp partials
    float D = 0.f;
    for (int c = 0; c < NC; c++) {
        D += g_d[c * BSN + bs] * __expf(g_m[c * BSN + bs] - m);
    }

    float lp = m - logf(D);                  // log_softmax at argmax
    float pr = expf(lp);
    float om = fmaxf(1.0f - pr, 1e-20f);
    g_pen[bs] = -logf(om);
    g_tok[bs] = best;
}

// ================================================================
// Kernel 3: 4-gram repeat mask + per-batch masked loss
// grid = B, block = 512 threads (one per position).
// ================================================================
__global__ __launch_bounds__(512) void k_mask()
{
    const int b = blockIdx.x;
    const int t = threadIdx.x;

    __shared__ int                tok[S];
    __shared__ unsigned long long key[S];   // P used
    __shared__ unsigned char      rep[S];   // P used
    __shared__ float              red[S];

    tok[t] = g_tok[b * S + t];
    rep[t] = 0;
    __syncthreads();

    if (t < P) {
        // tokens < 32000 < 2^15 -> pack 4-gram into 60 bits
        unsigned long long k =
              ((unsigned long long)tok[t]     << 45)
            | ((unsigned long long)tok[t + 1] << 30)
            | ((unsigned long long)tok[t + 2] << 15)
            |  (unsigned long long)tok[t + 3];
        key[t] = k;
    }
    __syncthreads();

    if (t < P) {
        unsigned long long k = key[t];
        unsigned char r = 0;
        for (int j = 0; j < t; j++) {
            if (key[j] == k) { r = 1; break; }
        }
        rep[t] = r;
    }
    __syncthreads();

    // mask[t] = OR rep[i] for i in [t-3, t] ∩ [0, P)
    int lo = t - 3 > 0 ? t - 3 : 0;
    int hi = t < P - 1 ? t : P - 1;
    bool msk = false;
    for (int i = lo; i <= hi; i++) msk |= (rep[i] != 0);

    red[t] = msk ? g_pen[b * S + t] : 0.0f;
    __syncthreads();

    // block tree-reduce
    for (int stride = 256; stride > 0; stride >>= 1) {
        if (t < stride) red[t] += red[t + stride];
        __syncthreads();
    }
    if (t == 0) g_bloss[b] = red[0];
}

// ================================================================
// Kernel 4: final scalar
// ================================================================
__global__ void k_final(float* __restrict__ out)
{
    float s = 0.f;
    for (int b = 0; b < B; b++) s += g_bloss[b];
    out[0] = s / (float)B;
}

// ================================================================
extern "C" void kernel_launch(void* const* d_in, const int* in_sizes, int n_in,
                              void* d_out, int out_size)
{
    const float* pred = (const float*)d_in[0];

    dim3 g1(NC, B);
    k_partial<<<g1, 128>>>(pred);
    k_combine<<<BSN / 256, 256>>>();
    k_mask<<<B, S>>>();
    k_final<<<1, 1>>>((float*)d_out);
}

// round 2
// speedup vs baseline: 1.0586x; 1.0586x over previous
#include <cuda_runtime.h>
#include <math.h>

#define B   8
#define V   32000
#define S   512
#define NC  125         // number of V-chunks in the argmax pass
#define VC  (V / NC)    // 256 v per chunk
#define BSN (B * S)     // 4096 (b,s) columns
#define P   (S - 4)     // 508 n-gram windows

// -------- scratch (device globals; no allocation allowed) --------
__device__ float g_cm [NC * BSN];   // per-chunk max          [c][bs]
__device__ int   g_cix[NC * BSN];   // per-chunk argmax       [c][bs]
__device__ float g_gm [BSN];        // global max per (b,s)
__device__ int   g_mask[BSN];       // ngram repeat mask
__device__ float g_pen [BSN];       // masked penalty (0 if unmasked)

// ================================================================
// Kernel 1: streaming argmax partials per V-chunk (memory bound).
// grid = (NC, B), block = 128 threads; thread owns 4 consecutive s
// via float4 loads (fully coalesced, 2KB per v-row per block).
// ================================================================
__global__ __launch_bounds__(128) void k_argmax(const float* __restrict__ pred)
{
    const int c = blockIdx.x;
    const int b = blockIdx.y;
    const int t = threadIdx.x;
    const int s0 = t * 4;

    const float* p = pred + (size_t)(b * V + c * VC) * S + s0;

    float m0 = -INFINITY, m1 = -INFINITY, m2 = -INFINITY, m3 = -INFINITY;
    int   i0 = 0, i1 = 0, i2 = 0, i3 = 0;

    int v = c * VC;
#pragma unroll 8
    for (int vv = 0; vv < VC; vv++, v++) {
        float4 x = *reinterpret_cast<const float4*>(p);
        p += S;
        // strict '>' + ascending v => first occurrence on exact ties
        if (x.x > m0) { m0 = x.x; i0 = v; }
        if (x.y > m1) { m1 = x.y; i1 = v; }
        if (x.z > m2) { m2 = x.z; i2 = v; }
        if (x.w > m3) { m3 = x.w; i3 = v; }
    }

    const int base = c * BSN + b * S + s0;     // 16B aligned
    *reinterpret_cast<float4*>(&g_cm [base]) = make_float4(m0, m1, m2, m3);
    *reinterpret_cast<int4*>  (&g_cix[base]) = make_int4(i0, i1, i2, i3);
}

// ================================================================
// Kernel 2: combine chunk partials -> tokens, then 4-gram repeat
// mask. grid = B, block = 512 (one thread per position s).
// ================================================================
__global__ __launch_bounds__(512) void k_maskfuse()
{
    const int b = blockIdx.x;
    const int t = threadIdx.x;
    const int bs = b * S + t;

    __shared__ int                tok[S];
    __shared__ unsigned long long key[S];
    __shared__ unsigned char      rep[S];

    // combine: ascending chunk order + strict '>' keeps first occurrence
    float m = -INFINITY;
    int best = 0;
    for (int c = 0; c < NC; c++) {
        float mc = g_cm[c * BSN + bs];
        if (mc > m) { m = mc; best = g_cix[c * BSN + bs]; }
    }
    g_gm[bs] = m;
    tok[t] = best;
    rep[t] = 0;
    __syncthreads();

    if (t < P) {
        // tokens < 32000 < 2^15 -> pack 4-gram into 60 bits
        key[t] = ((unsigned long long)tok[t]     << 45)
               | ((unsigned long long)tok[t + 1] << 30)
               | ((unsigned long long)tok[t + 2] << 15)
               |  (unsigned long long)tok[t + 3];
    }
    __syncthreads();

    if (t < P) {
        unsigned long long k = key[t];
        unsigned char r = 0;
        for (int j = 0; j < t; j++)
            if (key[j] == k) { r = 1; break; }
        rep[t] = r;
    }
    __syncthreads();

    // mask[t] = OR rep[i] for i in [t-3, t] ∩ [0, P)
    int lo = t - 3 > 0 ? t - 3 : 0;
    int hi = t < P - 1 ? t : P - 1;
    int msk = 0;
    for (int i = lo; i <= hi; i++) msk |= rep[i];

    g_mask[bs] = msk;
    g_pen[bs]  = 0.0f;    // k_lse overwrites only masked columns
}

// ================================================================
// Kernel 3: exact logsumexp ONLY for masked (b,s) columns.
// grid = BSN blocks of 128; unmasked blocks exit immediately.
// (Expected ~0 active blocks for random tokens; exact for any input.)
// ================================================================
__global__ __launch_bounds__(128) void k_lse(const float* __restrict__ pred)
{
    const int bs = blockIdx.x;
    if (!g_mask[bs]) return;

    const int b = bs / S;
    const int s = bs % S;
    const int t = threadIdx.x;
    const float m = g_gm[bs];

    const float* p = pred + (size_t)b * V * S + s;

    float d = 0.0f;
    for (int v = t; v < V; v += 128)
        d += __expf(p[(size_t)v * S] - m);

    // block reduce
    __shared__ float red[128];
    red[t] = d;
    __syncthreads();
    for (int st = 64; st > 0; st >>= 1) {
        if (t < st) red[t] += red[t + st];
        __syncthreads();
    }

    if (t == 0) {
        float D  = red[0];              // >= 1 (max term included)
        float lp = -logf(D);            // log_softmax at argmax = m - (m + logD)
        float pr = __expf(lp);
        float om = fmaxf(1.0f - pr, 1e-20f);
        g_pen[bs] = -logf(om);
    }
}

// ================================================================
// Kernel 4: final scalar = sum(pen) / B
// ================================================================
__global__ __launch_bounds__(512) void k_final(float* __restrict__ out)
{
    const int t = threadIdx.x;
    float s = 0.0f;
    for (int i = t; i < BSN; i += 512) s += g_pen[i];

    __shared__ float red[512];
    red[t] = s;
    __syncthreads();
    for (int st = 256; st > 0; st >>= 1) {
        if (t < st) red[t] += red[t + st];
        __syncthreads();
    }
    if (t == 0) out[0] = red[0] / (float)B;
}

// ================================================================
extern "C" void kernel_launch(void* const* d_in, const int* in_sizes, int n_in,
                              void* d_out, int out_size)
{
    const float* pred = (const float*)d_in[0];

    dim3 g1(NC, B);
    k_argmax<<<g1, 128>>>(pred);
    k_maskfuse<<<B, 512>>>();
    k_lse<<<BSN, 128>>>(pred);
    k_final<<<1, 512>>>((float*)d_out);
}